// round 1
// baseline (speedup 1.0000x reference)
#include <cuda_runtime.h>
#include <cstdint>

#define NPTS  60000
#define KNBR  27
#define CDIM  128
#define EPSBN 1e-5f
#define SLOPE 0.01f

// ---------------- device globals (no allocations allowed) ----------------
__device__ float    g_h1[(size_t)NPTS * CDIM];  // scratch for conv1 output / y1
__device__ float    g_sums[512];                // [0..255] conv1 sum/sumsq, [256..511] conv2
__device__ float    g_bn[512];                  // [off+c]=scale, [off+128+c]=shift
__device__ unsigned g_flags;
__device__ int      g_mask_mode;                // 0=f32, 1=i32, 2=u8/bool, 3=bf16

// ---------------- mask dtype detection ----------------
__global__ void zero_kernel() {
    int t = threadIdx.x;
    if (t < 512) g_sums[t] = 0.f;
    if (t == 0)  g_flags = 0u;
}

__global__ void detect_kernel(const unsigned* __restrict__ w, int nwords) {
    unsigned f = 0u;
    for (int i = blockIdx.x * blockDim.x + threadIdx.x; i < nwords;
         i += gridDim.x * blockDim.x) {
        unsigned v = w[i];
        if (v == 0x3F800000u)                         f |= 1u;  // f32 1.0 (or bf16 pair F,T)
        else if (v == 0x3F803F80u || v == 0x00003F80u) f |= 2u; // bf16-only patterns
        else if (v > 1u)                               f |= 4u; // packed bytes
    }
    if (f) atomicOr(&g_flags, f);
}

__global__ void resolve_kernel() {
    unsigned f = g_flags;
    int mode;
    if      (f & 2u) mode = 3;  // bf16
    else if (f & 1u) mode = 0;  // float32
    else if (f & 4u) mode = 2;  // uint8 / bool
    else             mode = 1;  // int32
    g_mask_mode = mode;
}

__device__ __forceinline__ float load_mask(const void* m, long i, int mode) {
    switch (mode) {
        case 0:  return ((const float*)m)[i];
        case 1:  return (float)(((const int*)m)[i] != 0);
        case 2:  return (float)(((const unsigned char*)m)[i] != 0);
        default: return (((const unsigned short*)m)[i] != 0) ? 1.f : 0.f;
    }
}

// ---------------- gather-GEMM: out[m,:] = sum_k mask[m,k]*x[nbr[m,k],:] @ W[k] ----------------
// Tile 128x128, K-chunks of 16 within one neighbor k at a time.
__global__ __launch_bounds__(256, 2)
void conv_gemm_kernel(const float* __restrict__ X, const int* __restrict__ nbr,
                      const void* __restrict__ mask, const float* __restrict__ W,
                      float* __restrict__ out)
{
    __shared__ float As[16][132];   // A transposed: As[ck][m], padded vs conflicts
    __shared__ float Bs[16][128];
    __shared__ int   s_nbr[128];
    __shared__ float s_msk[128];

    const int tid = threadIdx.x;
    const int tx  = tid & 15;
    const int ty  = tid >> 4;
    const int m0  = blockIdx.x * 128;
    const int mode = g_mask_mode;

    float acc[8][8];
    #pragma unroll
    for (int i = 0; i < 8; ++i)
        #pragma unroll
        for (int j = 0; j < 8; ++j) acc[i][j] = 0.f;

    for (int k = 0; k < KNBR; ++k) {
        // cache this k's neighbor column + mask for the 128 tile rows
        if (tid < 128) {
            int m = m0 + tid;
            int nb = 0; float mk = 0.f;
            if (m < NPTS) {
                long idx = (long)m * KNBR + k;
                nb = nbr[idx];
                mk = load_mask(mask, idx, mode);
            }
            s_nbr[tid] = nb;
            s_msk[tid] = mk;
        }
        __syncthreads();

        for (int cc = 0; cc < CDIM; cc += 16) {
            // ---- gather A tile: 128 rows x 16 channels (mask folded in) ----
            {
                const int q    = tid & 3;        // which float4 of the 16-chunk
                const int mrow = tid >> 2;       // 64 rows per pass
                #pragma unroll
                for (int p = 0; p < 2; ++p) {
                    int m = mrow + p * 64;
                    const float4 v = *reinterpret_cast<const float4*>(
                        X + (size_t)s_nbr[m] * CDIM + cc + q * 4);
                    float mk = s_msk[m];
                    As[q * 4 + 0][m] = v.x * mk;
                    As[q * 4 + 1][m] = v.y * mk;
                    As[q * 4 + 2][m] = v.z * mk;
                    As[q * 4 + 3][m] = v.w * mk;
                }
            }
            // ---- load B tile: W[k][cc:cc+16][0:128] ----
            {
                const int r0 = tid >> 5;           // 8 rows per pass
                const int cl = (tid & 31) * 4;
                const float* wp = W + (size_t)k * CDIM * CDIM;
                #pragma unroll
                for (int p = 0; p < 2; ++p) {
                    int r = r0 + p * 8;
                    *reinterpret_cast<float4*>(&Bs[r][cl]) =
                        *reinterpret_cast<const float4*>(wp + (size_t)(cc + r) * CDIM + cl);
                }
            }
            __syncthreads();

            #pragma unroll
            for (int ck = 0; ck < 16; ++ck) {
                float a[8], b[8];
                *(float4*)&a[0] = *(const float4*)&As[ck][ty * 8];
                *(float4*)&a[4] = *(const float4*)&As[ck][ty * 8 + 4];
                *(float4*)&b[0] = *(const float4*)&Bs[ck][tx * 8];
                *(float4*)&b[4] = *(const float4*)&Bs[ck][tx * 8 + 4];
                #pragma unroll
                for (int i = 0; i < 8; ++i)
                    #pragma unroll
                    for (int j = 0; j < 8; ++j)
                        acc[i][j] = fmaf(a[i], b[j], acc[i][j]);
            }
            __syncthreads();
        }
    }

    #pragma unroll
    for (int i = 0; i < 8; ++i) {
        int m = m0 + ty * 8 + i;
        if (m < NPTS) {
            float4 v0 = make_float4(acc[i][0], acc[i][1], acc[i][2], acc[i][3]);
            float4 v1 = make_float4(acc[i][4], acc[i][5], acc[i][6], acc[i][7]);
            *reinterpret_cast<float4*>(out + (size_t)m * CDIM + tx * 8)     = v0;
            *reinterpret_cast<float4*>(out + (size_t)m * CDIM + tx * 8 + 4) = v1;
        }
    }
}

// ---------------- BN stats: per-channel sum & sumsq ----------------
__global__ void stats_kernel(const float* __restrict__ h, int off) {
    int c    = threadIdx.x;                 // 128 channels
    int row0 = blockIdx.x * 512;
    int rend = min(row0 + 512, NPTS);
    float s = 0.f, sq = 0.f;
    for (int r = row0; r < rend; ++r) {
        float v = h[(size_t)r * CDIM + c];
        s += v; sq += v * v;
    }
    atomicAdd(&g_sums[off + c], s);
    atomicAdd(&g_sums[off + 128 + c], sq);
}

__global__ void finalize_kernel(const float* __restrict__ gamma,
                                const float* __restrict__ beta, int off) {
    int c = threadIdx.x;
    const float invN = 1.f / (float)NPTS;
    float mean = g_sums[off + c] * invN;
    float var  = g_sums[off + 128 + c] * invN - mean * mean;
    float sc   = gamma[c] / sqrtf(var + EPSBN);
    g_bn[off + c]       = sc;
    g_bn[off + 128 + c] = beta[c] - mean * sc;
}

// y = lrelu(bn1(h)) in place
__global__ void bn_lrelu_kernel(float* __restrict__ h) {
    int i = blockIdx.x * blockDim.x + threadIdx.x;
    if (i < NPTS * CDIM) {
        int c = i & 127;
        float v = fmaf(h[i], g_bn[c], g_bn[128 + c]);
        h[i] = v > 0.f ? v : SLOPE * v;
    }
}

// out = lrelu(bn2(h2) + x) in place on d_out
__global__ void bn_res_lrelu_kernel(float* __restrict__ h2, const float* __restrict__ x) {
    int i = blockIdx.x * blockDim.x + threadIdx.x;
    if (i < NPTS * CDIM) {
        int c = i & 127;
        float v = fmaf(h2[i], g_bn[256 + c], g_bn[384 + c]) + x[i];
        h2[i] = v > 0.f ? v : SLOPE * v;
    }
}

// ---------------- launch ----------------
extern "C" void kernel_launch(void* const* d_in, const int* in_sizes, int n_in,
                              void* d_out, int out_size)
{
    const float* x    = (const float*)d_in[0];
    const int*   nbr  = (const int*)d_in[1];
    const void*  mask = d_in[2];
    const float* W1   = (const float*)d_in[3];
    const float* W2   = (const float*)d_in[4];
    const float* g1   = (const float*)d_in[5];
    const float* b1   = (const float*)d_in[6];
    const float* g2   = (const float*)d_in[7];
    const float* b2   = (const float*)d_in[8];
    float* out = (float*)d_out;

    float* h1 = nullptr;
    cudaGetSymbolAddress((void**)&h1, g_h1);

    const int conv_blocks = (NPTS + 127) / 128;        // 469
    const int ew_blocks   = (NPTS * CDIM + 255) / 256; // 30000
    const int st_blocks   = (NPTS + 511) / 512;        // 118
    const int mask_words  = (NPTS * KNBR) / 4;         // 405000 (safe for every dtype)

    zero_kernel<<<1, 512>>>();
    detect_kernel<<<480, 256>>>((const unsigned*)mask, mask_words);
    resolve_kernel<<<1, 1>>>();

    conv_gemm_kernel<<<conv_blocks, 256>>>(x, nbr, mask, W1, h1);
    stats_kernel<<<st_blocks, 128>>>(h1, 0);
    finalize_kernel<<<1, 128>>>(g1, b1, 0);
    bn_lrelu_kernel<<<ew_blocks, 256>>>(h1);

    conv_gemm_kernel<<<conv_blocks, 256>>>(h1, nbr, mask, W2, out);
    stats_kernel<<<st_blocks, 128>>>(out, 256);
    finalize_kernel<<<1, 128>>>(g2, b2, 256);
    bn_res_lrelu_kernel<<<ew_blocks, 256>>>(out, x);
}